// round 16
// baseline (speedup 1.0000x reference)
#include <cuda_runtime.h>
#include <cuda_fp16.h>
#include <cstdint>

// Problem constants
#define BB 8
#define NN 2048
#define FF 256
#define CHUNKS (NN / 64)

// Scratch (allocation-free rule: __device__ globals)
__device__ __half g_xh[BB * NN * FF];    // x in f16              8.4 MB
__device__ __half g_Wh[FF * FF];         // W in f16
__device__ __half g_hTh[BB * FF * NN];   // h f16, [b][f][n]      8.4 MB
__device__ float g_wp1[4][FF];           // partial W^T a_src (4 row-groups)
__device__ float g_wp2[4][FF];           // partial W^T a_dst
__device__ float g_es1[BB * NN];         // exp(s_src)
__device__ float g_es2[BB * NN];         // exp(0.2*s_src)
__device__ uint32_t g_edEG[BB * NN];     // packed half2(e^s_dst, e^{.2 s_dst})

// ---------------------------------------------------------------------------
// helpers
// ---------------------------------------------------------------------------
__device__ __forceinline__ uint32_t smem_u32(const void* p) {
    uint32_t a;
    asm("{ .reg .u64 t; cvta.to.shared.u64 t, %1; cvt.u32.u64 %0, t; }"
        : "=r"(a) : "l"(p));
    return a;
}

__device__ __forceinline__ void cp16(uint32_t dst, const void* src) {
    asm volatile(
        "{ .reg .u64 g; cvta.to.global.u64 g, %1;"
        "  cp.async.cg.shared.global [%0], [g], 16; }"
        ::"r"(dst), "l"(src) : "memory");
}
#define CP_COMMIT() asm volatile("cp.async.commit_group;" ::: "memory")
#define CP_WAIT1() asm volatile("cp.async.wait_group 1;" ::: "memory")
#define CP_WAIT0() asm volatile("cp.async.wait_group 0;" ::: "memory")

__device__ __forceinline__ void ldsm4(uint32_t* r, uint32_t a) {
    asm volatile("ldmatrix.sync.aligned.m8n8.x4.shared.b16 {%0,%1,%2,%3}, [%4];"
                 : "=r"(r[0]), "=r"(r[1]), "=r"(r[2]), "=r"(r[3]) : "r"(a));
}

__device__ __forceinline__ void mma_f16(float* d, const uint32_t* a, uint32_t b0,
                                        uint32_t b1) {
    asm volatile(
        "mma.sync.aligned.m16n8k16.row.col.f32.f16.f16.f32 "
        "{%0,%1,%2,%3}, {%4,%5,%6,%7}, {%8,%9}, {%0,%1,%2,%3};"
        : "+f"(d[0]), "+f"(d[1]), "+f"(d[2]), "+f"(d[3])
        : "r"(a[0]), "r"(a[1]), "r"(a[2]), "r"(a[3]), "r"(b0), "r"(b1));
}

// tile row stride: 64 f16 + 8 pad = 144 bytes (9 x 16B -> conflict-free LDSM)
#define TSTRIDE 144

// ---------------------------------------------------------------------------
// wvec + cvt_w (coalesced): 4 blocks x 256 threads. Thread = k column; loop
// over this block's 64 o-rows with fully coalesced W row reads. Partials go
// to g_wp1/g_wp2[blk] (deterministic across graph replays; no atomics).
// Each block also converts its 1/4 slice of W to f16.
// ---------------------------------------------------------------------------
__global__ __launch_bounds__(256) void wvec_cvtw_kernel(const float* __restrict__ W,
                                                        const float* __restrict__ a_src,
                                                        const float* __restrict__ a_dst) {
    int t = threadIdx.x;        // k = t
    int blk = blockIdx.x;       // rows [blk*64, blk*64+64)
    float s1 = 0.f, s2 = 0.f;
    int o0 = blk * 64;
    #pragma unroll 8
    for (int q = 0; q < 64; q++) {
        int o = o0 + q;
        float w = W[(size_t)o * FF + t];   // coalesced across t
        s1 += a_src[o] * w;
        s2 += a_dst[o] * w;
    }
    g_wp1[blk][t] = s1;
    g_wp2[blk][t] = s2;

    // cvt_w slice: 4096 float4 per block, 16 per thread
    const float4* src = reinterpret_cast<const float4*>(W);
    __half2* dst = reinterpret_cast<__half2*>(g_Wh);
    #pragma unroll
    for (int q = 0; q < 16; q++) {
        int i = blk * 4096 + t + 256 * q;
        float4 v = src[i];
        dst[i * 2] = __floats2half2_rn(v.x, v.y);
        dst[i * 2 + 1] = __floats2half2_rn(v.z, v.w);
    }
}

// ---------------------------------------------------------------------------
// score + cvt_x: s_src = x.w_src, s_dst = x.w_dst (warp per row), and emit
// the f16 copy of x while the row is in registers. ws/wd staged from the 4
// wvec partials.
// ---------------------------------------------------------------------------
__global__ __launch_bounds__(256) void score_kernel(const float* __restrict__ x) {
    __shared__ float ws[FF], wd[FF];
    int t = threadIdx.x;
    ws[t] = g_wp1[0][t] + g_wp1[1][t] + g_wp1[2][t] + g_wp1[3][t];
    wd[t] = g_wp2[0][t] + g_wp2[1][t] + g_wp2[2][t] + g_wp2[3][t];
    __syncthreads();
    int warp = t >> 5, lane = t & 31;
    int g = blockIdx.x * 8 + warp;
    const float4* xr = reinterpret_cast<const float4*>(x + (size_t)g * FF);
    __half2* xo = reinterpret_cast<__half2*>(g_xh + (size_t)g * FF);
    float s1 = 0.f, s2 = 0.f;
    #pragma unroll
    for (int q = 0; q < 2; q++) {
        int idx = lane + 32 * q;
        float4 v = xr[idx];
        xo[idx * 2] = __floats2half2_rn(v.x, v.y);
        xo[idx * 2 + 1] = __floats2half2_rn(v.z, v.w);
        float4 w1 = *reinterpret_cast<const float4*>(&ws[idx * 4]);
        float4 w2 = *reinterpret_cast<const float4*>(&wd[idx * 4]);
        s1 += v.x * w1.x + v.y * w1.y + v.z * w1.z + v.w * w1.w;
        s2 += v.x * w2.x + v.y * w2.y + v.z * w2.z + v.w * w2.w;
    }
    #pragma unroll
    for (int o = 16; o; o >>= 1) {
        s1 += __shfl_xor_sync(0xFFFFFFFFu, s1, o);
        s2 += __shfl_xor_sync(0xFFFFFFFFu, s2, o);
    }
    if (lane == 0) {
        g_es1[g] = __expf(s1);
        g_es2[g] = __expf(0.2f * s1);
        float e1 = __expf(s2), e2 = __expf(0.2f * s2);
        __half2 pk = __floats2half2_rn(e1, e2);
        g_edEG[g] = *reinterpret_cast<uint32_t*>(&pk);
    }
}

// ---------------------------------------------------------------------------
// gemm_h v3: h_T[b][f][n] = sum_k W[f][k] * x[b][n][k]  (f16 mma, f32 accum)
// CTA tile m128(f) x n128, 512 threads = 16 warps (4m x 4n), warp m32 x n32.
// smem 73.7 KB, 2 CTAs/SM; grid 256 -> single balanced wave.
// ---------------------------------------------------------------------------
#define GH_SMEM (4 * 128 * TSTRIDE)   // A0,A1,X0,X1 each 128*144 = 73728 B
__global__ __launch_bounds__(512, 2) void gemm_h_kernel() {
    extern __shared__ char smraw[];
    uint32_t su = smem_u32(smraw);
    const uint32_t AB[2] = {su, su + 128 * TSTRIDE};
    const uint32_t XB[2] = {su + 2 * 128 * TSTRIDE, su + 3 * 128 * TSTRIDE};

    int t = threadIdx.x, l = t & 31, w = t >> 5;
    int b = blockIdx.z, n0 = blockIdx.x * 128, m0 = blockIdx.y * 128;
    int mbase = (w & 3) * 32, nbase = (w >> 2) * 32;
    int a_row = (l & 7) + ((l & 8) ? 8 : 0);
    int a_k = (l & 16) ? 16 : 0;
    int b_row = (l & 7) + ((l & 16) ? 8 : 0);
    int b_k = (l & 8) ? 16 : 0;

    const __half* Wsrc = g_Wh + (size_t)m0 * FF;
    const __half* Xsrc = g_xh + ((size_t)b * NN + n0) * FF;

    float acc[2][4][4] = {};

    #define GH_FILL(kc, s)                                                   \
        do {                                                                 \
            _Pragma("unroll")                                                \
            for (int q = 0; q < 2; q++) {                                    \
                int e = t + 512 * q;                                         \
                int fr = e >> 3, sg = e & 7;                                 \
                cp16(AB[s] + fr * TSTRIDE + sg * 16,                         \
                     Wsrc + (size_t)fr * FF + (kc) + sg * 8);                \
                cp16(XB[s] + fr * TSTRIDE + sg * 16,                         \
                     Xsrc + (size_t)fr * FF + (kc) + sg * 8);                \
            }                                                                \
            CP_COMMIT();                                                     \
        } while (0)

    GH_FILL(0, 0);
    for (int c = 0; c < 4; c++) {
        int s = c & 1;
        if (c < 3) GH_FILL((c + 1) * 64, s ^ 1);
        if (c < 3) CP_WAIT1(); else CP_WAIT0();
        __syncthreads();
        #pragma unroll
        for (int kk = 0; kk < 4; kk++) {
            uint32_t bf[2][4];
            #pragma unroll
            for (int g = 0; g < 2; g++)
                ldsm4(bf[g], XB[s] + (nbase + g * 16 + b_row) * TSTRIDE +
                                 kk * 32 + b_k);
            #pragma unroll
            for (int mt = 0; mt < 2; mt++) {
                uint32_t a[4];
                ldsm4(a, AB[s] + (mbase + mt * 16 + a_row) * TSTRIDE +
                             kk * 32 + a_k);
                #pragma unroll
                for (int g = 0; g < 2; g++) {
                    mma_f16(acc[mt][2 * g], a, bf[g][0], bf[g][1]);
                    mma_f16(acc[mt][2 * g + 1], a, bf[g][2], bf[g][3]);
                }
            }
        }
        __syncthreads();
    }

    #pragma unroll
    for (int mt = 0; mt < 2; mt++) {
        int f = m0 + mbase + mt * 16 + (l >> 2);
        #pragma unroll
        for (int nt = 0; nt < 4; nt++) {
            int n = n0 + nbase + nt * 8 + 2 * (l & 3);
            *reinterpret_cast<__half2*>(&g_hTh[((size_t)b * FF + f) * NN + n]) =
                __floats2half2_rn(acc[mt][nt][0], acc[mt][nt][1]);
            *reinterpret_cast<__half2*>(&g_hTh[((size_t)b * FF + f + 8) * NN + n]) =
                __floats2half2_rn(acc[mt][nt][2], acc[mt][nt][3]);
        }
    }
}

// ---------------------------------------------------------------------------
// attn: fused masked softmax + alpha @ h, f16 mma.  R15 structure (best
// measured): ITILE=64, 512 threads = 16 warps (2i x 8n), warp m32 x n32,
// 2 CTAs/SM, two-sync pipeline, HFILL(c+1) issued FIRST each chunk, e^s_dst
// factors packed half2 in smem. Micro-change vs R15: denominator accumulated
// from pre-rounding f32 p values (drops pack->unpack round trip; bias ~2^-12).
// p = adj * max(e^s_src * e^s_dst, e^{.2 s_src} * e^{.2 s_dst})  (exact lrelu)
// ---------------------------------------------------------------------------
#define ITILE 64
#define PBSZ (64 * TSTRIDE)                         // 9216
#define HBSZ (256 * TSTRIDE)                        // 36864
#define OFF_P0 0
#define OFF_P1 PBSZ
#define OFF_H0 (2 * PBSZ)                           // 18432
#define OFF_H1 (OFF_H0 + HBSZ)                      // 55296
#define OFF_SEG (OFF_H1 + HBSZ)                     // 92160, 8 KB packed
#define OFF_ES1 (OFF_SEG + NN * 4)                  // 100352
#define OFF_ES2 (OFF_ES1 + 256)
#define OFF_INVD (OFF_ES2 + 256)
#define AT_SMEM (OFF_INVD + 256)                    // 101120

__global__ __launch_bounds__(512, 2) void attn_kernel(const int* __restrict__ adj,
                                                      float* __restrict__ out) {
    extern __shared__ char smraw[];
    uint32_t su = smem_u32(smraw);
    uint32_t* sEG = reinterpret_cast<uint32_t*>(smraw + OFF_SEG);
    float* eS1 = reinterpret_cast<float*>(smraw + OFF_ES1);
    float* eS2 = reinterpret_cast<float*>(smraw + OFF_ES2);
    float* invd = reinterpret_cast<float*>(smraw + OFF_INVD);

    int t = threadIdx.x, l = t & 31, w = t >> 5;
    int b = blockIdx.y;
    int i0 = blockIdx.x * ITILE;

    for (int c = t; c < NN; c += 512) sEG[c] = g_edEG[b * NN + c];
    if (t < ITILE) {
        eS1[t] = g_es1[b * NN + i0 + t];
        eS2[t] = g_es2[b * NN + i0 + t];
    }
    __syncthreads();

    // p mapping: 8 threads/row, 8 j each (2 int4 adj quads, 4 uint2 factors)
    int pi = t >> 3, jq = t & 7;
    float E1 = eS1[pi], E2 = eS2[pi];
    const int4* adj_row = reinterpret_cast<const int4*>(
                              adj + ((size_t)b * NN + i0 + pi) * NN) + jq * 2;
    const uint2* sEG2 = reinterpret_cast<const uint2*>(sEG);
    float dreg = 0.f;

    // mma mapping: 2i x 8n warp grid, warp m32 x n32
    int mbase = (w & 1) * 32, nbase = (w >> 1) * 32;
    int a_row = (l & 7) + ((l & 8) ? 8 : 0);
    int a_k = (l & 16) ? 16 : 0;
    int b_row = (l & 7) + ((l & 16) ? 8 : 0);
    int b_k = (l & 8) ? 16 : 0;

    const __half* hsrc = g_hTh + (size_t)b * FF * NN;

    const uint32_t PB[2] = {su + OFF_P0, su + OFF_P1};
    const uint32_t HB[2] = {su + OFF_H0, su + OFF_H1};

    #define AT_HFILL(jc, s)                                                  \
        do {                                                                 \
            _Pragma("unroll")                                                \
            for (int l2 = 0; l2 < 4; l2++) {                                 \
                int e = t + 512 * l2;                                        \
                int fr = e >> 3, sg = e & 7;                                 \
                cp16(HB[s] + fr * TSTRIDE + sg * 16,                         \
                     hsrc + (size_t)fr * NN + (jc) + sg * 8);                \
            }                                                                \
            CP_COMMIT();                                                     \
        } while (0)

    int4 aR[2];
    aR[0] = adj_row[0];
    aR[1] = adj_row[1];
    AT_HFILL(0, 0);

    float acc[2][4][4] = {};

    for (int c = 0; c < CHUNKS; c++) {
        int s = c & 1;
        int jc = c * 64;

        // ---- issue h(c+1) cp.async FIRST (max flight time) ----
        if (c + 1 < CHUNKS) AT_HFILL(jc + 64, s ^ 1);

        // ---- p(c) from prefetched adj regs (packed factor loads) ----
        {
            uint32_t pk[4];
            int jb2 = (jc >> 1) + jq * 4;   // uint2 index (pairs of packed u32)
            #pragma unroll
            for (int q = 0; q < 2; q++) {
                int4 av = aR[q];
                uint2 ua = sEG2[jb2 + q * 2];
                uint2 ub = sEG2[jb2 + q * 2 + 1];
                float2 f0 = __half22float2(*reinterpret_cast<__half2*>(&ua.x));
                float2 f1 = __half22float2(*reinterpret_cast<__half2*>(&ua.y));
                float2 f2 = __half22float2(*reinterpret_cast<__half2*>(&ub.x));
                float2 f3 = __half22float2(*reinterpret_cast<__half2*>(&ub.y));
                float p0 = fmaxf(E1 * f0.x, E2 * f0.y);
                float p1 = fmaxf(E1 * f1.x, E2 * f1.y);
                float p2 = fmaxf(E1 * f2.x, E2 * f2.y);
                float p3 = fmaxf(E1 * f3.x, E2 * f3.y);
                p0 = av.x ? p0 : 0.f;
                p1 = av.y ? p1 : 0.f;
                p2 = av.z ? p2 : 0.f;
                p3 = av.w ? p3 : 0.f;
                dreg += (p0 + p1) + (p2 + p3);   // pre-rounding f32 denominator
                __half2 h0 = __floats2half2_rn(p0, p1);
                __half2 h1 = __floats2half2_rn(p2, p3);
                pk[q * 2] = *reinterpret_cast<uint32_t*>(&h0);
                pk[q * 2 + 1] = *reinterpret_cast<uint32_t*>(&h1);
            }
            uint32_t pa = PB[s] + pi * TSTRIDE + jq * 16;
            asm volatile("st.shared.v4.b32 [%0], {%1,%2,%3,%4};" ::"r"(pa),
                         "r"(pk[0]), "r"(pk[1]), "r"(pk[2]), "r"(pk[3]) : "memory");
        }
        // ---- prefetch adj(c+1) ----
        if (c + 1 < CHUNKS) {
            aR[0] = adj_row[(c + 1) * 16];
            aR[1] = adj_row[(c + 1) * 16 + 1];
            CP_WAIT1();
        } else {
            CP_WAIT0();
        }
        __syncthreads();

        // ---- f16 tensor-core GEMM on buffers s ----
        #pragma unroll
        for (int kk = 0; kk < 4; kk++) {
            uint32_t bf[2][4];
            #pragma unroll
            for (int g = 0; g < 2; g++)
                ldsm4(bf[g], HB[s] + (nbase + g * 16 + b_row) * TSTRIDE +
                                 kk * 32 + b_k);
            #pragma unroll
            for (int mt = 0; mt < 2; mt++) {
                uint32_t a[4];
                ldsm4(a, PB[s] + (mbase + mt * 16 + a_row) * TSTRIDE +
                             kk * 32 + a_k);
                #pragma unroll
                for (int g = 0; g < 2; g++) {
                    mma_f16(acc[mt][2 * g], a, bf[g][0], bf[g][1]);
                    mma_f16(acc[mt][2 * g + 1], a, bf[g][2], bf[g][3]);
                }
            }
        }
        __syncthreads();
    }

    // ---- denominators (8 threads per row -> shfl over 3 levels) ----
    dreg += __shfl_xor_sync(0xFFFFFFFFu, dreg, 1);
    dreg += __shfl_xor_sync(0xFFFFFFFFu, dreg, 2);
    dreg += __shfl_xor_sync(0xFFFFFFFFu, dreg, 4);
    if ((t & 7) == 0) invd[pi] = (dreg > 0.f) ? (1.f / dreg) : 0.f;
    __syncthreads();

    // ---- epilogue ----
    #pragma unroll
    for (int mt = 0; mt < 2; mt++) {
        int lr = mbase + mt * 16 + (l >> 2);
        float s0 = invd[lr], s1v = invd[lr + 8];
        float* o0 = out + ((size_t)b * NN + i0 + lr) * FF + nbase;
        float* o1 = o0 + (size_t)8 * FF;
        #pragma unroll
        for (int nt = 0; nt < 4; nt++) {
            int cofs = nt * 8 + 2 * (l & 3);
            *reinterpret_cast<float2*>(o0 + cofs) =
                make_float2(acc[mt][nt][0] * s0, acc[mt][nt][1] * s0);
            *reinterpret_cast<float2*>(o1 + cofs) =
                make_float2(acc[mt][nt][2] * s1v, acc[mt][nt][3] * s1v);
        }
    }
}

// ---------------------------------------------------------------------------
extern "C" void kernel_launch(void* const* d_in, const int* in_sizes, int n_in,
                              void* d_out, int out_size) {
    const float* x     = (const float*)d_in[0];  // (B,N,F_in)
    const int*   adj   = (const int*)d_in[1];    // (B,N,N)
    const float* W     = (const float*)d_in[2];  // (F_out,F_in)
    const float* a_src = (const float*)d_in[3];  // (F_out)
    const float* a_dst = (const float*)d_in[4];  // (F_out)
    float* out = (float*)d_out;                  // (B,N,F_out)

    (void)in_sizes; (void)n_in; (void)out_size;

    // w = W^T a partials (coalesced, 4 blocks) + W f16 conversion
    wvec_cvtw_kernel<<<4, 256>>>(W, a_src, a_dst);
    // scores (sums partials) + x f16 conversion
    score_kernel<<<(BB * NN) / 8, 256>>>(x);
    // h_T = W @ x^T (f16 tensor cores, m128xn128, 512 thr, single wave)
    cudaFuncSetAttribute(gemm_h_kernel, cudaFuncAttributeMaxDynamicSharedMemorySize,
                         GH_SMEM);
    gemm_h_kernel<<<dim3(NN / 128, FF / 128, BB), 512, GH_SMEM>>>();
    // fused masked softmax + alpha @ h (R15 structure, f32 denominator)
    cudaFuncSetAttribute(attn_kernel, cudaFuncAttributeMaxDynamicSharedMemorySize,
                         AT_SMEM);
    attn_kernel<<<dim3(NN / ITILE, BB), 512, AT_SMEM>>>(adj, out);
}

// round 17
// speedup vs baseline: 1.0664x; 1.0664x over previous
#include <cuda_runtime.h>
#include <cuda_fp16.h>
#include <cstdint>

// Problem constants
#define BB 8
#define NN 2048
#define FF 256
#define CHUNKS (NN / 64)

// Scratch (allocation-free rule: __device__ globals)
__device__ __half g_xh[BB * NN * FF];    // x in f16              8.4 MB
__device__ __half g_Wh[FF * FF];         // W in f16
__device__ __half g_hTh[BB * FF * NN];   // h f16, [b][f][n]      8.4 MB
__device__ float g_wsrc[FF];             // W^T a_src
__device__ float g_wdst[FF];             // W^T a_dst
__device__ float g_es1[BB * NN];         // exp(s_src)
__device__ float g_es2[BB * NN];         // exp(0.2*s_src)
__device__ uint32_t g_edEG[BB * NN];     // packed half2(e^s_dst, e^{.2 s_dst})

// ---------------------------------------------------------------------------
// helpers
// ---------------------------------------------------------------------------
__device__ __forceinline__ uint32_t smem_u32(const void* p) {
    uint32_t a;
    asm("{ .reg .u64 t; cvta.to.shared.u64 t, %1; cvt.u32.u64 %0, t; }"
        : "=r"(a) : "l"(p));
    return a;
}

__device__ __forceinline__ void cp16(uint32_t dst, const void* src) {
    asm volatile(
        "{ .reg .u64 g; cvta.to.global.u64 g, %1;"
        "  cp.async.cg.shared.global [%0], [g], 16; }"
        ::"r"(dst), "l"(src) : "memory");
}
#define CP_COMMIT() asm volatile("cp.async.commit_group;" ::: "memory")
#define CP_WAIT1() asm volatile("cp.async.wait_group 1;" ::: "memory")
#define CP_WAIT0() asm volatile("cp.async.wait_group 0;" ::: "memory")

__device__ __forceinline__ void ldsm4(uint32_t* r, uint32_t a) {
    asm volatile("ldmatrix.sync.aligned.m8n8.x4.shared.b16 {%0,%1,%2,%3}, [%4];"
                 : "=r"(r[0]), "=r"(r[1]), "=r"(r[2]), "=r"(r[3]) : "r"(a));
}

__device__ __forceinline__ void mma_f16(float* d, const uint32_t* a, uint32_t b0,
                                        uint32_t b1) {
    asm volatile(
        "mma.sync.aligned.m16n8k16.row.col.f32.f16.f16.f32 "
        "{%0,%1,%2,%3}, {%4,%5,%6,%7}, {%8,%9}, {%0,%1,%2,%3};"
        : "+f"(d[0]), "+f"(d[1]), "+f"(d[2]), "+f"(d[3])
        : "r"(a[0]), "r"(a[1]), "r"(a[2]), "r"(a[3]), "r"(b0), "r"(b1));
}

// tile row stride: 64 f16 + 8 pad = 144 bytes (9 x 16B -> conflict-free LDSM)
#define TSTRIDE 144

// ---------------------------------------------------------------------------
// wvec + cvt_w (R15-proven): w_src[k] = sum_o a_src[o]*W[o][k], warp per k,
// 32 blocks x 256 threads (parallelism beats coalescing at this size),
// plus f32->f16 conversion of W in the same kernel.
// ---------------------------------------------------------------------------
__global__ __launch_bounds__(256) void wvec_cvtw_kernel(const float* __restrict__ W,
                                                        const float* __restrict__ a_src,
                                                        const float* __restrict__ a_dst) {
    int t = threadIdx.x, lane = t & 31, warp = t >> 5;
    int k = blockIdx.x * 8 + warp;     // 0..255
    float s1 = 0.f, s2 = 0.f;
    #pragma unroll
    for (int q = 0; q < 8; q++) {
        int o = lane + 32 * q;
        float w = W[(size_t)o * FF + k];
        s1 += a_src[o] * w;
        s2 += a_dst[o] * w;
    }
    #pragma unroll
    for (int o = 16; o; o >>= 1) {
        s1 += __shfl_xor_sync(0xFFFFFFFFu, s1, o);
        s2 += __shfl_xor_sync(0xFFFFFFFFu, s2, o);
    }
    if (lane == 0) {
        g_wsrc[k] = s1;
        g_wdst[k] = s2;
    }
    const float4* src = reinterpret_cast<const float4*>(W);
    __half2* dst = reinterpret_cast<__half2*>(g_Wh);
    int gt = blockIdx.x * 256 + t;
    #pragma unroll
    for (int q = 0; q < 2; q++) {
        int i = gt + 8192 * q;
        float4 v = src[i];
        dst[i * 2] = __floats2half2_rn(v.x, v.y);
        dst[i * 2 + 1] = __floats2half2_rn(v.z, v.w);
    }
}

// ---------------------------------------------------------------------------
// score + cvt_x: s_src = x.w_src, s_dst = x.w_dst (warp per row), and emit
// the f16 copy of x while the row is in registers.
// ---------------------------------------------------------------------------
__global__ __launch_bounds__(256) void score_kernel(const float* __restrict__ x) {
    __shared__ float ws[FF], wd[FF];
    int t = threadIdx.x;
    ws[t] = g_wsrc[t];
    wd[t] = g_wdst[t];
    __syncthreads();
    int warp = t >> 5, lane = t & 31;
    int g = blockIdx.x * 8 + warp;
    const float4* xr = reinterpret_cast<const float4*>(x + (size_t)g * FF);
    __half2* xo = reinterpret_cast<__half2*>(g_xh + (size_t)g * FF);
    float s1 = 0.f, s2 = 0.f;
    #pragma unroll
    for (int q = 0; q < 2; q++) {
        int idx = lane + 32 * q;
        float4 v = xr[idx];
        xo[idx * 2] = __floats2half2_rn(v.x, v.y);
        xo[idx * 2 + 1] = __floats2half2_rn(v.z, v.w);
        float4 w1 = *reinterpret_cast<const float4*>(&ws[idx * 4]);
        float4 w2 = *reinterpret_cast<const float4*>(&wd[idx * 4]);
        s1 += v.x * w1.x + v.y * w1.y + v.z * w1.z + v.w * w1.w;
        s2 += v.x * w2.x + v.y * w2.y + v.z * w2.z + v.w * w2.w;
    }
    #pragma unroll
    for (int o = 16; o; o >>= 1) {
        s1 += __shfl_xor_sync(0xFFFFFFFFu, s1, o);
        s2 += __shfl_xor_sync(0xFFFFFFFFu, s2, o);
    }
    if (lane == 0) {
        g_es1[g] = __expf(s1);
        g_es2[g] = __expf(0.2f * s1);
        float e1 = __expf(s2), e2 = __expf(0.2f * s2);
        __half2 pk = __floats2half2_rn(e1, e2);
        g_edEG[g] = *reinterpret_cast<uint32_t*>(&pk);
    }
}

// ---------------------------------------------------------------------------
// gemm_h v3: h_T[b][f][n] = sum_k W[f][k] * x[b][n][k]  (f16 mma, f32 accum)
// CTA tile m128(f) x n128, 512 threads = 16 warps (4m x 4n), warp m32 x n32.
// smem 73.7 KB, 2 CTAs/SM; grid 256 -> single balanced wave.
// ---------------------------------------------------------------------------
#define GH_SMEM (4 * 128 * TSTRIDE)   // A0,A1,X0,X1 each 128*144 = 73728 B
__global__ __launch_bounds__(512, 2) void gemm_h_kernel() {
    extern __shared__ char smraw[];
    uint32_t su = smem_u32(smraw);
    const uint32_t AB[2] = {su, su + 128 * TSTRIDE};
    const uint32_t XB[2] = {su + 2 * 128 * TSTRIDE, su + 3 * 128 * TSTRIDE};

    int t = threadIdx.x, l = t & 31, w = t >> 5;
    int b = blockIdx.z, n0 = blockIdx.x * 128, m0 = blockIdx.y * 128;
    int mbase = (w & 3) * 32, nbase = (w >> 2) * 32;
    int a_row = (l & 7) + ((l & 8) ? 8 : 0);
    int a_k = (l & 16) ? 16 : 0;
    int b_row = (l & 7) + ((l & 16) ? 8 : 0);
    int b_k = (l & 8) ? 16 : 0;

    const __half* Wsrc = g_Wh + (size_t)m0 * FF;
    const __half* Xsrc = g_xh + ((size_t)b * NN + n0) * FF;

    float acc[2][4][4] = {};

    #define GH_FILL(kc, s)                                                   \
        do {                                                                 \
            _Pragma("unroll")                                                \
            for (int q = 0; q < 2; q++) {                                    \
                int e = t + 512 * q;                                         \
                int fr = e >> 3, sg = e & 7;                                 \
                cp16(AB[s] + fr * TSTRIDE + sg * 16,                         \
                     Wsrc + (size_t)fr * FF + (kc) + sg * 8);                \
                cp16(XB[s] + fr * TSTRIDE + sg * 16,                         \
                     Xsrc + (size_t)fr * FF + (kc) + sg * 8);                \
            }                                                                \
            CP_COMMIT();                                                     \
        } while (0)

    GH_FILL(0, 0);
    for (int c = 0; c < 4; c++) {
        int s = c & 1;
        if (c < 3) GH_FILL((c + 1) * 64, s ^ 1);
        if (c < 3) CP_WAIT1(); else CP_WAIT0();
        __syncthreads();
        #pragma unroll
        for (int kk = 0; kk < 4; kk++) {
            uint32_t bf[2][4];
            #pragma unroll
            for (int g = 0; g < 2; g++)
                ldsm4(bf[g], XB[s] + (nbase + g * 16 + b_row) * TSTRIDE +
                                 kk * 32 + b_k);
            #pragma unroll
            for (int mt = 0; mt < 2; mt++) {
                uint32_t a[4];
                ldsm4(a, AB[s] + (mbase + mt * 16 + a_row) * TSTRIDE +
                             kk * 32 + a_k);
                #pragma unroll
                for (int g = 0; g < 2; g++) {
                    mma_f16(acc[mt][2 * g], a, bf[g][0], bf[g][1]);
                    mma_f16(acc[mt][2 * g + 1], a, bf[g][2], bf[g][3]);
                }
            }
        }
        __syncthreads();
    }

    #pragma unroll
    for (int mt = 0; mt < 2; mt++) {
        int f = m0 + mbase + mt * 16 + (l >> 2);
        #pragma unroll
        for (int nt = 0; nt < 4; nt++) {
            int n = n0 + nbase + nt * 8 + 2 * (l & 3);
            *reinterpret_cast<__half2*>(&g_hTh[((size_t)b * FF + f) * NN + n]) =
                __floats2half2_rn(acc[mt][nt][0], acc[mt][nt][1]);
            *reinterpret_cast<__half2*>(&g_hTh[((size_t)b * FF + f + 8) * NN + n]) =
                __floats2half2_rn(acc[mt][nt][2], acc[mt][nt][3]);
        }
    }
}

// ---------------------------------------------------------------------------
// attn: fused masked softmax + alpha @ h, f16 mma.  Best measured structure:
// ITILE=64, 512 threads = 16 warps (2i x 8n), warp m32 x n32, 2 CTAs/SM,
// two-sync pipeline, HFILL(c+1) issued FIRST each chunk, e^s_dst factors
// packed half2 in smem, f32 pre-rounding denominator.
// p = adj * max(e^s_src * e^s_dst, e^{.2 s_src} * e^{.2 s_dst})  (exact lrelu)
// ---------------------------------------------------------------------------
#define ITILE 64
#define PBSZ (64 * TSTRIDE)                         // 9216
#define HBSZ (256 * TSTRIDE)                        // 36864
#define OFF_P0 0
#define OFF_P1 PBSZ
#define OFF_H0 (2 * PBSZ)                           // 18432
#define OFF_H1 (OFF_H0 + HBSZ)                      // 55296
#define OFF_SEG (OFF_H1 + HBSZ)                     // 92160, 8 KB packed
#define OFF_ES1 (OFF_SEG + NN * 4)                  // 100352
#define OFF_ES2 (OFF_ES1 + 256)
#define OFF_INVD (OFF_ES2 + 256)
#define AT_SMEM (OFF_INVD + 256)                    // 101120

__global__ __launch_bounds__(512, 2) void attn_kernel(const int* __restrict__ adj,
                                                      float* __restrict__ out) {
    extern __shared__ char smraw[];
    uint32_t su = smem_u32(smraw);
    uint32_t* sEG = reinterpret_cast<uint32_t*>(smraw + OFF_SEG);
    float* eS1 = reinterpret_cast<float*>(smraw + OFF_ES1);
    float* eS2 = reinterpret_cast<float*>(smraw + OFF_ES2);
    float* invd = reinterpret_cast<float*>(smraw + OFF_INVD);

    int t = threadIdx.x, l = t & 31, w = t >> 5;
    int b = blockIdx.y;
    int i0 = blockIdx.x * ITILE;

    for (int c = t; c < NN; c += 512) sEG[c] = g_edEG[b * NN + c];
    if (t < ITILE) {
        eS1[t] = g_es1[b * NN + i0 + t];
        eS2[t] = g_es2[b * NN + i0 + t];
    }
    __syncthreads();

    // p mapping: 8 threads/row, 8 j each (2 int4 adj quads, 4 uint2 factors)
    int pi = t >> 3, jq = t & 7;
    float E1 = eS1[pi], E2 = eS2[pi];
    const int4* adj_row = reinterpret_cast<const int4*>(
                              adj + ((size_t)b * NN + i0 + pi) * NN) + jq * 2;
    const uint2* sEG2 = reinterpret_cast<const uint2*>(sEG);
    float dreg = 0.f;

    // mma mapping: 2i x 8n warp grid, warp m32 x n32
    int mbase = (w & 1) * 32, nbase = (w >> 1) * 32;
    int a_row = (l & 7) + ((l & 8) ? 8 : 0);
    int a_k = (l & 16) ? 16 : 0;
    int b_row = (l & 7) + ((l & 16) ? 8 : 0);
    int b_k = (l & 8) ? 16 : 0;

    const __half* hsrc = g_hTh + (size_t)b * FF * NN;

    const uint32_t PB[2] = {su + OFF_P0, su + OFF_P1};
    const uint32_t HB[2] = {su + OFF_H0, su + OFF_H1};

    #define AT_HFILL(jc, s)                                                  \
        do {                                                                 \
            _Pragma("unroll")                                                \
            for (int l2 = 0; l2 < 4; l2++) {                                 \
                int e = t + 512 * l2;                                        \
                int fr = e >> 3, sg = e & 7;                                 \
                cp16(HB[s] + fr * TSTRIDE + sg * 16,                         \
                     hsrc + (size_t)fr * NN + (jc) + sg * 8);                \
            }                                                                \
            CP_COMMIT();                                                     \
        } while (0)

    int4 aR[2];
    aR[0] = adj_row[0];
    aR[1] = adj_row[1];
    AT_HFILL(0, 0);

    float acc[2][4][4] = {};

    for (int c = 0; c < CHUNKS; c++) {
        int s = c & 1;
        int jc = c * 64;

        // ---- issue h(c+1) cp.async FIRST (max flight time) ----
        if (c + 1 < CHUNKS) AT_HFILL(jc + 64, s ^ 1);

        // ---- p(c) from prefetched adj regs (packed factor loads) ----
        {
            uint32_t pk[4];
            int jb2 = (jc >> 1) + jq * 4;   // uint2 index (pairs of packed u32)
            #pragma unroll
            for (int q = 0; q < 2; q++) {
                int4 av = aR[q];
                uint2 ua = sEG2[jb2 + q * 2];
                uint2 ub = sEG2[jb2 + q * 2 + 1];
                float2 f0 = __half22float2(*reinterpret_cast<__half2*>(&ua.x));
                float2 f1 = __half22float2(*reinterpret_cast<__half2*>(&ua.y));
                float2 f2 = __half22float2(*reinterpret_cast<__half2*>(&ub.x));
                float2 f3 = __half22float2(*reinterpret_cast<__half2*>(&ub.y));
                float p0 = fmaxf(E1 * f0.x, E2 * f0.y);
                float p1 = fmaxf(E1 * f1.x, E2 * f1.y);
                float p2 = fmaxf(E1 * f2.x, E2 * f2.y);
                float p3 = fmaxf(E1 * f3.x, E2 * f3.y);
                p0 = av.x ? p0 : 0.f;
                p1 = av.y ? p1 : 0.f;
                p2 = av.z ? p2 : 0.f;
                p3 = av.w ? p3 : 0.f;
                dreg += (p0 + p1) + (p2 + p3);   // pre-rounding f32 denominator
                __half2 h0 = __floats2half2_rn(p0, p1);
                __half2 h1 = __floats2half2_rn(p2, p3);
                pk[q * 2] = *reinterpret_cast<uint32_t*>(&h0);
                pk[q * 2 + 1] = *reinterpret_cast<uint32_t*>(&h1);
            }
            uint32_t pa = PB[s] + pi * TSTRIDE + jq * 16;
            asm volatile("st.shared.v4.b32 [%0], {%1,%2,%3,%4};" ::"r"(pa),
                         "r"(pk[0]), "r"(pk[1]), "r"(pk[2]), "r"(pk[3]) : "memory");
        }
        // ---- prefetch adj(c+1) ----
        if (c + 1 < CHUNKS) {
            aR[0] = adj_row[(c + 1) * 16];
            aR[1] = adj_row[(c + 1) * 16 + 1];
            CP_WAIT1();
        } else {
            CP_WAIT0();
        }
        __syncthreads();

        // ---- f16 tensor-core GEMM on buffers s ----
        #pragma unroll
        for (int kk = 0; kk < 4; kk++) {
            uint32_t bf[2][4];
            #pragma unroll
            for (int g = 0; g < 2; g++)
                ldsm4(bf[g], HB[s] + (nbase + g * 16 + b_row) * TSTRIDE +
                                 kk * 32 + b_k);
            #pragma unroll
            for (int mt = 0; mt < 2; mt++) {
                uint32_t a[4];
                ldsm4(a, PB[s] + (mbase + mt * 16 + a_row) * TSTRIDE +
                             kk * 32 + a_k);
                #pragma unroll
                for (int g = 0; g < 2; g++) {
                    mma_f16(acc[mt][2 * g], a, bf[g][0], bf[g][1]);
                    mma_f16(acc[mt][2 * g + 1], a, bf[g][2], bf[g][3]);
                }
            }
        }
        __syncthreads();
    }

    // ---- denominators (8 threads per row -> shfl over 3 levels) ----
    dreg += __shfl_xor_sync(0xFFFFFFFFu, dreg, 1);
    dreg += __shfl_xor_sync(0xFFFFFFFFu, dreg, 2);
    dreg += __shfl_xor_sync(0xFFFFFFFFu, dreg, 4);
    if ((t & 7) == 0) invd[pi] = (dreg > 0.f) ? (1.f / dreg) : 0.f;
    __syncthreads();

    // ---- epilogue ----
    #pragma unroll
    for (int mt = 0; mt < 2; mt++) {
        int lr = mbase + mt * 16 + (l >> 2);
        float s0 = invd[lr], s1v = invd[lr + 8];
        float* o0 = out + ((size_t)b * NN + i0 + lr) * FF + nbase;
        float* o1 = o0 + (size_t)8 * FF;
        #pragma unroll
        for (int nt = 0; nt < 4; nt++) {
            int cofs = nt * 8 + 2 * (l & 3);
            *reinterpret_cast<float2*>(o0 + cofs) =
                make_float2(acc[mt][nt][0] * s0, acc[mt][nt][1] * s0);
            *reinterpret_cast<float2*>(o1 + cofs) =
                make_float2(acc[mt][nt][2] * s1v, acc[mt][nt][3] * s1v);
        }
    }
}

// ---------------------------------------------------------------------------
extern "C" void kernel_launch(void* const* d_in, const int* in_sizes, int n_in,
                              void* d_out, int out_size) {
    const float* x     = (const float*)d_in[0];  // (B,N,F_in)
    const int*   adj   = (const int*)d_in[1];    // (B,N,N)
    const float* W     = (const float*)d_in[2];  // (F_out,F_in)
    const float* a_src = (const float*)d_in[3];  // (F_out)
    const float* a_dst = (const float*)d_in[4];  // (F_out)
    float* out = (float*)d_out;                  // (B,N,F_out)

    (void)in_sizes; (void)n_in; (void)out_size;

    // w = W^T a (warp-per-k, 32 blocks — R15-proven) + W f16 conversion
    wvec_cvtw_kernel<<<32, 256>>>(W, a_src, a_dst);
    // scores + x f16 conversion, one kernel
    score_kernel<<<(BB * NN) / 8, 256>>>(x);
    // h_T = W @ x^T (f16 tensor cores, m128xn128, 512 thr, single wave)
    cudaFuncSetAttribute(gemm_h_kernel, cudaFuncAttributeMaxDynamicSharedMemorySize,
                         GH_SMEM);
    gemm_h_kernel<<<dim3(NN / 128, FF / 128, BB), 512, GH_SMEM>>>();
    // fused masked softmax + alpha @ h (best measured structure)
    cudaFuncSetAttribute(attn_kernel, cudaFuncAttributeMaxDynamicSharedMemorySize,
                         AT_SMEM);
    attn_kernel<<<dim3(NN / ITILE, BB), 512, AT_SMEM>>>(adj, out);
}